// round 7
// baseline (speedup 1.0000x reference)
#include <cuda_runtime.h>
#include <math.h>

#define TT 2048
#define DIN 256
#define L0N 64
#define NT 512

typedef unsigned long long u64;

// ---------------- device scratch ----------------
__device__ float g_h1buf[TT + 1][512 * 8];   // full h1 history [j*8+b]
__device__ float g_h2[2][512 * 8];           // ping-pong h2
__device__ unsigned g_l0f[64];
__device__ unsigned g_l1f[64];

// ---------------- dynamic smem (floats) ----------------
// srcU [512*8] | srcW [512*8] | redS [16][16][18]
#define OFF_W   4096
#define OFF_RED 8192
#define SMEM_FLOATS (8192 + 16 * 16 * 18)
#define SMEM_BYTES (SMEM_FLOATS * 4)   // 51200 B

__device__ __forceinline__ u64 pk2(float x) {
    u64 r; asm("mov.b64 %0, {%1, %1};" : "=l"(r) : "f"(x)); return r;
}
__device__ __forceinline__ void fma2(u64& a, u64 b, u64 c) {
    asm("fma.rn.f32x2 %0, %1, %2, %0;" : "+l"(a) : "l"(b), "l"(c));
}
__device__ __forceinline__ u64 addp(u64 a, u64 b) {
    u64 r; asm("add.rn.f32x2 %0, %1, %2;" : "=l"(r) : "l"(a), "l"(b)); return r;
}
__device__ __forceinline__ float4 ldcg4(const float4* p) { return __ldcg(p); }
__device__ __forceinline__ unsigned ldacq(const unsigned* p) {
    unsigned v;
    asm volatile("ld.acquire.gpu.global.u32 %0, [%1];" : "=r"(v) : "l"(p) : "memory");
    return v;
}
__device__ __forceinline__ void strel(unsigned* p, unsigned v) {
    asm volatile("st.release.gpu.global.u32 [%0], %1;" :: "l"(p), "r"(v) : "memory");
}
// warp-collective: wait until all 64 flags >= tgt
__device__ __forceinline__ void poll64(const unsigned* f, unsigned tgt, int lane) {
    for (;;) {
        unsigned a = ldacq(f + lane);
        unsigned b = ldacq(f + 32 + lane);
        if (__all_sync(0xffffffffu, (a >= tgt) && (b >= tgt))) return;
    }
}

#define BARW asm volatile("bar.sync 1, 256;" ::: "memory")
#define BARU asm volatile("bar.sync 2, 256;" ::: "memory")

template <int KS>
__device__ __forceinline__ void gemv(const float* __restrict__ src, int kbase,
                                     const float (&wr)[64], u64 (&acc)[8]) {
    #pragma unroll
    for (int kk = 0; kk < KS; ++kk) {
        const ulonglong2* hp = (const ulonglong2*)(src + (kbase + kk) * 8);
        ulonglong2 hA = hp[0], hB = hp[1];
        u64 w0 = pk2(wr[2 * kk]), w1 = pk2(wr[2 * kk + 1]);
        fma2(acc[0], w0, hA.x); fma2(acc[1], w0, hA.y);
        fma2(acc[2], w0, hB.x); fma2(acc[3], w0, hB.y);
        fma2(acc[4], w1, hA.x); fma2(acc[5], w1, hA.y);
        fma2(acc[6], w1, hB.x); fma2(acc[7], w1, hB.y);
    }
}

__global__ void init_k() {
    int t = threadIdx.x;
    for (int i = t; i < 512 * 8; i += 256) g_h1buf[0][i] = 0.f;
    float* h2f = (float*)g_h2;
    for (int i = t; i < 2 * 512 * 8; i += 256) h2f[i] = 0.f;
    if (t < 64) { g_l0f[t] = 0u; g_l1f[t] = 0u; }
}

template <int LAYER>
__device__ void run_layer(const float* __restrict__ x,
                          const float* __restrict__ wW,  // input-projection weights
                          const float* __restrict__ uW,  // recurrent weights
                          const float* __restrict__ bW,
                          const float* __restrict__ bU,
                          int lcta, float* sm, float* __restrict__ out)
{
    float* srcU = sm;
    float* srcW = sm + OFF_W;
    float* redS = sm + OFF_RED;

    const int t    = threadIdx.x;
    const int lane = t & 31;
    const int widx = t >> 5;          // 0..15
    const bool isW = (t < 256);
    const int tt   = t & 255;
    const int jg   = tt & 15;         // rows jg*2, jg*2+1 (row = unit*4+gate)
    const int kgv  = tt >> 4;         // 0..15
    const int ubase = lcta * 8;

    const int row0 = jg * 2, row1 = row0 + 1;
    const int grow0 = (row0 & 3) * 512 + ubase + (row0 >> 2);
    const int grow1 = (row1 & 3) * 512 + ubase + (row1 >> 2);

    // ---- weights into registers ----
    float wr[64];
    if (isW) {
        if (LAYER == 0) {
            #pragma unroll
            for (int kk = 0; kk < 16; ++kk) {
                int k = kgv * 16 + kk;
                wr[2 * kk]     = wW[grow0 * 256 + k];
                wr[2 * kk + 1] = wW[grow1 * 256 + k];
            }
        } else {
            #pragma unroll
            for (int kk = 0; kk < 32; ++kk) {
                int k = kgv * 32 + kk;
                wr[2 * kk]     = wW[grow0 * 512 + k];
                wr[2 * kk + 1] = wW[grow1 * 512 + k];
            }
        }
    } else {
        #pragma unroll
        for (int kk = 0; kk < 32; ++kk) {
            int k = kgv * 32 + kk;
            wr[2 * kk]     = uW[grow0 * 512 + k];
            wr[2 * kk + 1] = uW[grow1 * 512 + k];
        }
    }

    float biasv = 0.f, c_state = 0.f;
    int gu = t >> 5, gg = (t >> 3) & 3, gb = t & 7;   // gate-phase role (isW)
    if (isW) {
        int gr = gg * 512 + ubase + gu;
        biasv = bW[gr] + bU[gr];
    }
    const int grow_row = gu * 4 + gg;
    const int gjgr = grow_row >> 1, grbit = grow_row & 1;

    for (int r = 0; r < TT; ++r) {
        u64 acc[8];
        #pragma unroll
        for (int i = 0; i < 8; ++i) acc[i] = 0ull;

        if (isW) {
            // ---------- W branch (off the self-loop) ----------
            if (LAYER == 0) {
                // stage x[r]: b = t&7, d4 = t>>3 (and +32)
                const int b = t & 7, d4 = t >> 3;
                const float* xp = x + ((size_t)b * TT + r) * DIN;
                float4 xa = *(const float4*)(xp + d4 * 4);
                float4 xb2 = *(const float4*)(xp + (d4 + 32) * 4);
                float* p = srcW + (d4 * 4) * 8 + b;
                p[0] = xa.x; p[8] = xa.y; p[16] = xa.z; p[24] = xa.w;
                float* q = srcW + ((d4 + 32) * 4) * 8 + b;
                q[0] = xb2.x; q[8] = xb2.y; q[16] = xb2.z; q[24] = xb2.w;
            } else {
                poll64(g_l0f, (unsigned)(r + 1), lane);
                const float4* s = (const float4*)g_h1buf[r + 1];
                float4* d = (float4*)srcW;
                #pragma unroll
                for (int i = 0; i < 4; ++i) d[t + i * 256] = ldcg4(s + t + i * 256);
            }
            BARW;
            if (LAYER == 0) gemv<16>(srcW, kgv * 16, wr, acc);
            else            gemv<32>(srcW, kgv * 32, wr, acc);
        } else {
            // ---------- U branch (the self-loop) ----------
            if (LAYER == 0) {
                poll64(g_l0f, (unsigned)r, lane);
                const float4* s = (const float4*)g_h1buf[r];
                float4* d = (float4*)srcU;
                #pragma unroll
                for (int i = 0; i < 4; ++i) d[tt + i * 256] = ldcg4(s + tt + i * 256);
            } else {
                poll64(g_l1f, (unsigned)r, lane);
                const float4* s = (const float4*)g_h2[(r + 1) & 1];
                float4* d = (float4*)srcU;
                #pragma unroll
                for (int i = 0; i < 4; ++i) d[tt + i * 256] = ldcg4(s + tt + i * 256);
            }
            BARU;
            gemv<32>(srcU, kgv * 32, wr, acc);
        }

        // in-warp k reduce (2 kg per warp) + partial store
        #pragma unroll
        for (int i = 0; i < 8; ++i)
            acc[i] = addp(acc[i], __shfl_xor_sync(0xffffffffu, acc[i], 16));
        if ((lane & 16) == 0) {
            u64* rb = (u64*)(redS + (widx * 16 + jg) * 18);
            #pragma unroll
            for (int i = 0; i < 8; ++i) rb[i] = acc[i];
        }
        __syncthreads();   // the ONE full barrier

        if (isW) {
            // gate sum + activation (256 threads, one gate each)
            float s = biasv;
            #pragma unroll
            for (int w2 = 0; w2 < 16; ++w2)
                s += redS[(w2 * 16 + gjgr) * 18 + grbit * 8 + gb];
            float v;
            if (gg == 2) { float e = __expf(2.f * s); v = 1.f - __fdividef(2.f, e + 1.f); }
            else         { float e = __expf(-s);      v = __fdividef(1.f, 1.f + e); }
            // gather 4 gates of (unit gu, batch b) into lanes 0..7
            float ai = __shfl_sync(0xffffffffu, v, gb);
            float af = __shfl_sync(0xffffffffu, v, 8 + gb);
            float ag = __shfl_sync(0xffffffffu, v, 16 + gb);
            float ao = __shfl_sync(0xffffffffu, v, 24 + gb);
            if (lane < 8) {
                c_state = af * c_state + ai * ag;
                float h = ao * fmaxf(c_state, 0.f);
                const int j = ubase + gu;
                if (LAYER == 0) {
                    __stcg(&g_h1buf[r + 1][j * 8 + gb], h);
                    if (r == TT - 1) {
                        out[8388608 + gb * 512 + j] = h;        // hh[0]
                        out[8396800 + gb * 512 + j] = c_state;  // cc[0]
                    }
                } else {
                    __stcg(&g_h2[r & 1][j * 8 + gb], h);
                    out[((size_t)(gb * TT + r)) * 512 + j] = h; // h2 sequence
                    if (r == TT - 1) {
                        out[8388608 + 4096 + gb * 512 + j] = h;        // hh[1]
                        out[8396800 + 4096 + gb * 512 + j] = c_state;  // cc[1]
                    }
                }
            }
            BARW;
            if (t == 0) strel(LAYER == 0 ? &g_l0f[lcta] : &g_l1f[lcta],
                              (unsigned)(r + 1));
        }
        // U-warps: next round's poll blocks on own flag => implicit sync
    }
}

__global__ void __launch_bounds__(NT, 1)
lstm_persist(const float* __restrict__ x,
             const float* __restrict__ w0w, const float* __restrict__ w0b,
             const float* __restrict__ u0w, const float* __restrict__ u0b,
             const float* __restrict__ w1w, const float* __restrict__ w1b,
             const float* __restrict__ u1w, const float* __restrict__ u1b,
             float* __restrict__ out)
{
    extern __shared__ float sm[];
    const int cta = blockIdx.x;
    if (cta < L0N)
        run_layer<0>(x, w0w, u0w, w0b, u0b, cta, sm, out);
    else
        run_layer<1>(x, w1w, u1w, w1b, u1b, cta - L0N, sm, out);
}

extern "C" void kernel_launch(void* const* d_in, const int* in_sizes, int n_in,
                              void* d_out, int out_size)
{
    const float* x    = (const float*)d_in[0];
    const float* w0_w = (const float*)d_in[1];
    const float* w0_b = (const float*)d_in[2];
    const float* u0_w = (const float*)d_in[3];
    const float* u0_b = (const float*)d_in[4];
    const float* w1_w = (const float*)d_in[5];
    const float* w1_b = (const float*)d_in[6];
    const float* u1_w = (const float*)d_in[7];
    const float* u1_b = (const float*)d_in[8];
    float* out = (float*)d_out;

    static int attr_done = 0;
    if (!attr_done) {
        cudaFuncSetAttribute(lstm_persist, cudaFuncAttributeMaxDynamicSharedMemorySize, SMEM_BYTES);
        attr_done = 1;
    }

    init_k<<<1, 256>>>();
    lstm_persist<<<128, NT, SMEM_BYTES>>>(x, w0_w, w0_b, u0_w, u0_b,
                                          w1_w, w1_b, u1_w, u1_b, out);
}

// round 8
// speedup vs baseline: 2.3825x; 2.3825x over previous
#include <cuda_runtime.h>
#include <math.h>

// Problem constants
#define BB 8
#define TT 2048
#define DIN 256
#define HH 512
#define G4 2048
#define MM (BB*TT)
#define NCTA 96
#define L0N 32
#define NT 512

typedef unsigned long long u64;

// ---------------- device scratch ----------------
__device__ float g_wx0[(size_t)MM * G4];   // 128MB: x@W0^T + (w0_b+u0_b)
__device__ float g_h1[2][HH * BB];         // ping-pong h1 [j*8+b]
__device__ float g_h2[2][HH * BB];         // ping-pong h2
__device__ unsigned g_bar;

// ---------------- dynamic smem (floats) ----------------
// hS   [8192]            (L1: h1 @0, h2 @4096; L0: h1 @0)
// redS [16][520]  @8192  (stride 520)
// actS [512]      @16512
#define OFF_RED 8192
#define OFF_ACT 16512
#define SMEM_FLOATS 17024
#define SMEM_BYTES (SMEM_FLOATS * 4)

__device__ __forceinline__ u64 pk2(float x) {
    u64 r; asm("mov.b64 %0, {%1, %1};" : "=l"(r) : "f"(x)); return r;
}
__device__ __forceinline__ void fma2(u64& a, u64 b, u64 c) {
    asm("fma.rn.f32x2 %0, %1, %2, %0;" : "+l"(a) : "l"(b), "l"(c));
}
__device__ __forceinline__ u64 addp(u64 a, u64 b) {
    u64 r; asm("add.rn.f32x2 %0, %1, %2;" : "=l"(r) : "l"(a), "l"(b)); return r;
}
__device__ __forceinline__ float4 ldcg4(const float4* p) { return __ldcg(p); }
__device__ __forceinline__ float fast_sig(float x) {
    return __fdividef(1.f, 1.f + __expf(-x));
}
__device__ __forceinline__ float fast_tanh(float x) {
    float e = __expf(2.f * x);
    return 1.f - __fdividef(2.f, e + 1.f);
}

__global__ void __launch_bounds__(NT, 1)
lstm_persist(const float* __restrict__ u0w,
             const float* __restrict__ w1w, const float* __restrict__ u1w,
             const float* __restrict__ w1b, const float* __restrict__ u1b,
             float* __restrict__ out)
{
    extern __shared__ float sm[];
    float* hS   = sm;
    float* redS = sm + OFF_RED;
    float* actS = sm + OFF_ACT;

    const int t   = threadIdx.x;
    const int cta = blockIdx.x;
    const int lane = t & 31;

    float wr[64];
    u64 acc[8];
    float c_state = 0.f;

    if (cta < L0N) {
        // =============== LAYER 0: U0*h1, R=64 rows (16 units x 4 gates) ===============
        const int ubase = cta * 16;
        const int jp = t & 31;          // row-pair
        const int kg = t >> 5;          // 0..15 (== warp id)
        {
            const int lr0 = 2 * jp, lr1 = lr0 + 1;
            const int g0 = (lr0 >> 4) * 512 + ubase + (lr0 & 15);
            const int g1 = (lr1 >> 4) * 512 + ubase + (lr1 & 15);
            #pragma unroll 8
            for (int kk = 0; kk < 32; ++kk) {
                int k = kg * 32 + kk;
                wr[2 * kk]     = u0w[(size_t)g0 * 512 + k];
                wr[2 * kk + 1] = u0w[(size_t)g1 * 512 + k];
            }
        }
        // act-phase role: value index t -> row=t>>3, b=t&7
        const int arow = t >> 3, ab = t & 7;
        const int agate = arow >> 4;
        const size_t wxoff = ((size_t)(ab * TT)) * G4 + agate * 512 + ubase + (arow & 15);
        __syncthreads();

        for (int r = 0; r <= TT; ++r) {
            const bool active = (r < TT);
            float wxv = 0.f;
            if (active) {
                wxv = __ldg(&g_wx0[wxoff + (size_t)r * G4]);   // early, hides latency
                // stage h1[prev]
                const float4* s = (const float4*)g_h1[(r + 1) & 1];
                float4* d = (float4*)hS;
                d[t] = ldcg4(s + t);
                d[t + 512] = ldcg4(s + t + 512);
            }
            __syncthreads();

            if (active) {
                #pragma unroll
                for (int i = 0; i < 8; ++i) acc[i] = 0ull;
                const int kbase = kg * 32;
                #pragma unroll 8
                for (int kk = 0; kk < 32; ++kk) {
                    const u64* hp = (const u64*)(hS + (kbase + kk) * 8);
                    u64 hA0 = hp[0], hA1 = hp[1], hB0 = hp[2], hB1 = hp[3];
                    u64 w0 = pk2(wr[2 * kk]), w1 = pk2(wr[2 * kk + 1]);
                    fma2(acc[0], w0, hA0); fma2(acc[1], w0, hA1);
                    fma2(acc[2], w0, hB0); fma2(acc[3], w0, hB1);
                    fma2(acc[4], w1, hA0); fma2(acc[5], w1, hA1);
                    fma2(acc[6], w1, hB0); fma2(acc[7], w1, hB1);
                }
                u64* rb = (u64*)(redS + kg * 520 + jp * 16);
                #pragma unroll
                for (int i = 0; i < 8; ++i) rb[i] = acc[i];
            }
            __syncthreads();

            if (active) {
                float s = wxv;
                #pragma unroll
                for (int k2 = 0; k2 < 16; ++k2) s += redS[k2 * 520 + t];
                actS[t] = (agate == 2) ? fast_tanh(s) : fast_sig(s);
            }
            __syncthreads();

            if (active && t < 128) {
                const int u = t >> 3, b = t & 7;
                float ai = actS[u * 8 + b];
                float af = actS[128 + u * 8 + b];
                float ag = actS[256 + u * 8 + b];
                float ao = actS[384 + u * 8 + b];
                c_state = af * c_state + ai * ag;
                float h = ao * fmaxf(c_state, 0.f);
                const int j = ubase + u;
                __stcg(&g_h1[r & 1][j * 8 + b], h);
                if (r == TT - 1) {
                    out[8388608 + b * 512 + j] = h;        // hh[0]
                    out[8396800 + b * 512 + j] = c_state;  // cc[0]
                }
            }

            if (r < TT) {
                __syncthreads();
                if (t == 0) {
                    asm volatile("red.release.gpu.global.add.u32 [%0], 1;"
                                 :: "l"(&g_bar) : "memory");
                    const unsigned target = (unsigned)NCTA * (unsigned)(r + 1);
                    unsigned v;
                    do {
                        asm volatile("ld.acquire.gpu.global.u32 %0, [%1];"
                                     : "=r"(v) : "l"(&g_bar) : "memory");
                    } while (v < target);
                }
                __syncthreads();
            }
        }
    } else {
        // =============== LAYER 1: [W1|U1]*[h1;h2], R=32 rows (8 units x 4 gates) =====
        const int lcta  = cta - L0N;
        const int ubase = lcta * 8;
        const int jp = t & 15;          // row-pair 0..15
        const int kg = t >> 4;          // 0..31
        {
            const int lr0 = 2 * jp, lr1 = lr0 + 1;
            const int g0 = (lr0 >> 3) * 512 + ubase + (lr0 & 7);
            const int g1 = (lr1 >> 3) * 512 + ubase + (lr1 & 7);
            #pragma unroll 8
            for (int kk = 0; kk < 32; ++kk) {
                int k = kg * 32 + kk;
                if (k < 512) {
                    wr[2 * kk]     = w1w[(size_t)g0 * 512 + k];
                    wr[2 * kk + 1] = w1w[(size_t)g1 * 512 + k];
                } else {
                    wr[2 * kk]     = u1w[(size_t)g0 * 512 + (k - 512)];
                    wr[2 * kk + 1] = u1w[(size_t)g1 * 512 + (k - 512)];
                }
            }
        }
        float biasv = 0.f;
        const int arow = t >> 3, ab = t & 7;
        const int agate = arow >> 3;    // valid for t<256
        if (t < 256) {
            int gr = agate * 512 + ubase + (arow & 7);
            biasv = w1b[gr] + u1b[gr];
        }
        __syncthreads();

        for (int r = 0; r <= TT; ++r) {
            const bool active = (r >= 1);
            if (active) {
                const int slot = (r + 1) & 1;
                const float4* s1 = (const float4*)g_h1[slot];
                const float4* s2 = (const float4*)g_h2[slot];
                float4* d = (float4*)hS;
                d[t]        = ldcg4(s1 + t);
                d[t + 512]  = ldcg4(s1 + t + 512);
                d[t + 1024] = ldcg4(s2 + t);
                d[t + 1536] = ldcg4(s2 + t + 512);
            }
            __syncthreads();

            if (active) {
                #pragma unroll
                for (int i = 0; i < 8; ++i) acc[i] = 0ull;
                const int kbase = kg * 32;
                #pragma unroll 8
                for (int kk = 0; kk < 32; ++kk) {
                    const u64* hp = (const u64*)(hS + (kbase + kk) * 8);
                    u64 hA0 = hp[0], hA1 = hp[1], hB0 = hp[2], hB1 = hp[3];
                    u64 w0 = pk2(wr[2 * kk]), w1 = pk2(wr[2 * kk + 1]);
                    fma2(acc[0], w0, hA0); fma2(acc[1], w0, hA1);
                    fma2(acc[2], w0, hB0); fma2(acc[3], w0, hB1);
                    fma2(acc[4], w1, hA0); fma2(acc[5], w1, hA1);
                    fma2(acc[6], w1, hB0); fma2(acc[7], w1, hB1);
                }
                // combine kg pairs within warp (lane^16 has other kg, same jp)
                #pragma unroll
                for (int i = 0; i < 8; ++i)
                    acc[i] = addp(acc[i], __shfl_xor_sync(0xffffffffu, acc[i], 16));
                if (lane < 16) {
                    u64* rb = (u64*)(redS + (t >> 5) * 520 + jp * 16);
                    #pragma unroll
                    for (int i = 0; i < 8; ++i) rb[i] = acc[i];
                }
            }
            __syncthreads();

            if (active && t < 256) {
                float s = biasv;
                #pragma unroll
                for (int k2 = 0; k2 < 16; ++k2) s += redS[k2 * 520 + t];
                actS[t] = (agate == 2) ? fast_tanh(s) : fast_sig(s);
            }
            __syncthreads();

            if (active && t < 64) {
                const int u = t >> 3, b = t & 7;
                float ai = actS[u * 8 + b];
                float af = actS[64 + u * 8 + b];
                float ag = actS[128 + u * 8 + b];
                float ao = actS[192 + u * 8 + b];
                c_state = af * c_state + ai * ag;
                float h = ao * fmaxf(c_state, 0.f);
                const int j = ubase + u;
                __stcg(&g_h2[r & 1][j * 8 + b], h);
                out[((size_t)(b * TT + (r - 1))) * HH + j] = h;   // h2 sequence
                if (r == TT) {
                    out[8388608 + 4096 + b * 512 + j] = h;        // hh[1]
                    out[8396800 + 4096 + b * 512 + j] = c_state;  // cc[1]
                }
            }

            if (r < TT) {
                __syncthreads();
                if (t == 0) {
                    asm volatile("red.release.gpu.global.add.u32 [%0], 1;"
                                 :: "l"(&g_bar) : "memory");
                    const unsigned target = (unsigned)NCTA * (unsigned)(r + 1);
                    unsigned v;
                    do {
                        asm volatile("ld.acquire.gpu.global.u32 %0, [%1];"
                                     : "=r"(v) : "l"(&g_bar) : "memory");
                    } while (v < target);
                }
                __syncthreads();
            }
        }
    }
}

// ---------------- kernel 1: wx0 = x @ w0^T + (w0_b + u0_b), plus state reset ----------------
__global__ void wx_gemm(const float* __restrict__ X, const float* __restrict__ W,
                        const float* __restrict__ b0, const float* __restrict__ ub0)
{
    __shared__ float As[16][128];
    __shared__ float Bs[16][128];
    const int bn = blockIdx.x, bm = blockIdx.y;
    const int t = threadIdx.x;

    if (bn == 0 && bm == 0) {
        float* h1f = (float*)g_h1;
        float* h2f = (float*)g_h2;
        for (int i = t; i < 2 * HH * BB; i += 256) { h1f[i] = 0.f; h2f[i] = 0.f; }
        if (t == 0) g_bar = 0u;
    }

    const int tm = t & 15, tn = t >> 4;
    u64 accp[8][4];
    #pragma unroll
    for (int i = 0; i < 8; ++i)
        #pragma unroll
        for (int j = 0; j < 4; ++j) accp[i][j] = 0ull;

    for (int kt = 0; kt < DIN; kt += 16) {
        #pragma unroll
        for (int i = 0; i < 2; ++i) {
            int f = t * 2 + i;
            int row = f >> 2, kq = f & 3;
            float4 a = *(const float4*)&X[(size_t)(bm * 128 + row) * DIN + kt + kq * 4];
            As[kq * 4 + 0][row] = a.x; As[kq * 4 + 1][row] = a.y;
            As[kq * 4 + 2][row] = a.z; As[kq * 4 + 3][row] = a.w;
            float4 bv = *(const float4*)&W[(size_t)(bn * 128 + row) * DIN + kt + kq * 4];
            Bs[kq * 4 + 0][row] = bv.x; Bs[kq * 4 + 1][row] = bv.y;
            Bs[kq * 4 + 2][row] = bv.z; Bs[kq * 4 + 3][row] = bv.w;
        }
        __syncthreads();
        #pragma unroll
        for (int k = 0; k < 16; ++k) {
            float4 a0 = *(const float4*)&As[k][tm * 8];
            float4 a1 = *(const float4*)&As[k][tm * 8 + 4];
            const ulonglong2* bp = (const ulonglong2*)&Bs[k][tn * 8];
            ulonglong2 c01 = bp[0];
            ulonglong2 c23 = bp[1];
            float av[8] = {a0.x, a0.y, a0.z, a0.w, a1.x, a1.y, a1.z, a1.w};
            #pragma unroll
            for (int i = 0; i < 8; ++i) {
                u64 wp = pk2(av[i]);
                fma2(accp[i][0], wp, c01.x);
                fma2(accp[i][1], wp, c01.y);
                fma2(accp[i][2], wp, c23.x);
                fma2(accp[i][3], wp, c23.y);
            }
        }
        __syncthreads();
    }

    const int gbase = bn * 128 + tn * 8;
    float bias[8];
    #pragma unroll
    for (int j = 0; j < 8; ++j) bias[j] = __ldg(&b0[gbase + j]) + __ldg(&ub0[gbase + j]);
    #pragma unroll
    for (int i = 0; i < 8; ++i) {
        const int m = bm * 128 + tm * 8 + i;
        float v[8];
        #pragma unroll
        for (int p = 0; p < 4; ++p) {
            float lo, hi;
            asm("mov.b64 {%0, %1}, %2;" : "=f"(lo), "=f"(hi) : "l"(accp[i][p]));
            v[2 * p] = lo; v[2 * p + 1] = hi;
        }
        float4 o0 = make_float4(v[0] + bias[0], v[1] + bias[1],
                                v[2] + bias[2], v[3] + bias[3]);
        float4 o1 = make_float4(v[4] + bias[4], v[5] + bias[5],
                                v[6] + bias[6], v[7] + bias[7]);
        *(float4*)&g_wx0[(size_t)m * G4 + gbase]     = o0;
        *(float4*)&g_wx0[(size_t)m * G4 + gbase + 4] = o1;
    }
}

extern "C" void kernel_launch(void* const* d_in, const int* in_sizes, int n_in,
                              void* d_out, int out_size)
{
    const float* x    = (const float*)d_in[0];
    const float* w0_w = (const float*)d_in[1];
    const float* w0_b = (const float*)d_in[2];
    const float* u0_w = (const float*)d_in[3];
    const float* u0_b = (const float*)d_in[4];
    const float* w1_w = (const float*)d_in[5];
    const float* w1_b = (const float*)d_in[6];
    const float* u1_w = (const float*)d_in[7];
    const float* u1_b = (const float*)d_in[8];
    float* out = (float*)d_out;

    static int attr_done = 0;
    if (!attr_done) {
        cudaFuncSetAttribute(lstm_persist, cudaFuncAttributeMaxDynamicSharedMemorySize, SMEM_BYTES);
        attr_done = 1;
    }

    wx_gemm<<<dim3(G4 / 128, MM / 128), 256>>>(x, w0_w, w0_b, u0_b);
    lstm_persist<<<NCTA, NT, SMEM_BYTES>>>(u0_w, w1_w, u1_w, w1_b, u1_b, out);
}